// round 14
// baseline (speedup 1.0000x reference)
#include <cuda_runtime.h>
#include <cuda_bf16.h>

#define BATCH 256
#define SEQ   128
#define EDIM  512
#define HD    256
#define G4    1024
#define NTAG  76
#define MROWS 32768   // SEQ*BATCH
#define WST   264     // recurrence smem row stride (bf16), conflict-free ldmatrix
#define BST   520     // emis B smem row stride (bf16)

// ---------------- scratch (device globals; no runtime allocation) ----------------
__device__ float d_Zf[(size_t)MROWS * G4];   // input proj fwd, (S,B,4HD), gate order i,f,g,o
__device__ float d_Zb[(size_t)MROWS * G4];   // input proj bwd
__device__ float d_em[(size_t)MROWS * NTAG]; // emissions (S,B,T)
__device__ float d_llh[BATCH];

__device__ __align__(16) __nv_bfloat16 d_Hh[(size_t)MROWS * 512];  // feats bf16: [r][hf|hb]
__device__ __align__(16) __nv_bfloat16 d_Hbf[2 * 2 * BATCH * HD];  // ping [parity][dir][b][hu]
__device__ __align__(16) __nv_bfloat16 d_Abf[(size_t)MROWS * EDIM]; // gathered embeddings
__device__ __align__(16) __nv_bfloat16 d_Wbf[(size_t)2048 * EDIM];  // [Wf;Wb] bf16
__device__ __align__(16) __nv_bfloat16 d_WoutBf[80 * EDIM];         // Wout bf16, padded 80 rows
__device__ float d_biasZ[2048];                                     // b_ih+b_hh both dirs

__device__ __forceinline__ float sigm(float x)  { return 1.0f / (1.0f + __expf(-x)); }
// fast HW gates (recurrence only): tanh.approx + sigmoid via tanh identity
__device__ __forceinline__ float tanha(float x) {
    float y; asm("tanh.approx.f32 %0, %1;" : "=f"(y) : "f"(x)); return y;
}
__device__ __forceinline__ float sigma(float x) { return fmaf(tanha(x * 0.5f), 0.5f, 0.5f); }

// ================= baseline-PTX tensor helpers (no sm_103a-gated instrs) =================
__device__ __forceinline__ unsigned smem_u32(const void* p) {
    unsigned a;
    asm("{ .reg .u64 t; cvta.to.shared.u64 t, %1; cvt.u32.u64 %0, t; }" : "=r"(a) : "l"(p));
    return a;
}
__device__ __forceinline__ void ldsm4(unsigned& r0, unsigned& r1, unsigned& r2, unsigned& r3,
                                      unsigned addr) {
    asm volatile("ldmatrix.sync.aligned.m8n8.x4.shared.b16 {%0,%1,%2,%3}, [%4];"
                 : "=r"(r0), "=r"(r1), "=r"(r2), "=r"(r3) : "r"(addr));
}
__device__ __forceinline__ void mma16816(float* d, const unsigned* a, const unsigned* b) {
    asm volatile(
        "mma.sync.aligned.m16n8k16.row.col.f32.bf16.bf16.f32 "
        "{%0,%1,%2,%3}, {%4,%5,%6,%7}, {%8,%9}, {%0,%1,%2,%3};"
        : "+f"(d[0]), "+f"(d[1]), "+f"(d[2]), "+f"(d[3])
        : "r"(a[0]), "r"(a[1]), "r"(a[2]), "r"(a[3]), "r"(b[0]), "r"(b[1]));
}
__device__ __forceinline__ void cpasync16(unsigned dst, const void* src) {
    asm volatile("cp.async.cg.shared.global [%0], [%1], 16;" :: "r"(dst), "l"(src));
}
#define CP_COMMIT() asm volatile("cp.async.commit_group;" ::: "memory")
#define CP_WAIT(n)  asm volatile("cp.async.wait_group %0;" :: "n"(n) : "memory")
#define CLUSTER_ARRIVE() asm volatile("barrier.cluster.arrive.aligned;" ::: "memory")
#define CLUSTER_WAIT()   asm volatile("barrier.cluster.wait.aligned;" ::: "memory")
#define NB_SYNC(id) asm volatile("bar.sync %0, 128;" :: "r"(id) : "memory")

// ---------------- init: h0 -> bf16 ping parity 0 ----------------
__global__ void k_init(const float* __restrict__ h0)
{
    int i = blockIdx.x * 256 + threadIdx.x;   // grid 512 -> 131072 exact
    d_Hbf[i] = __float2bfloat16(h0[i]);
}

// ---------------- convert weights + bias ----------------
__global__ void k_convW(const float* __restrict__ Wf, const float* __restrict__ Wb,
                        const float* __restrict__ bihf, const float* __restrict__ bhhf,
                        const float* __restrict__ bihb, const float* __restrict__ bhhb)
{
    int j = blockIdx.x;   // 0..2047
    const float* src = (j < 1024) ? (Wf + (size_t)j * EDIM) : (Wb + (size_t)(j - 1024) * EDIM);
    float4 v = ((const float4*)src)[threadIdx.x];   // 128 threads * 4 = 512
    __nv_bfloat162* dst = (__nv_bfloat162*)(d_Wbf + (size_t)j * EDIM);
    dst[threadIdx.x * 2 + 0] = __floats2bfloat162_rn(v.x, v.y);
    dst[threadIdx.x * 2 + 1] = __floats2bfloat162_rn(v.z, v.w);
    if (threadIdx.x == 0)
        d_biasZ[j] = (j < 1024) ? (bihf[j] + bhhf[j]) : (bihb[j - 1024] + bhhb[j - 1024]);
}

__global__ void k_convO(const float* __restrict__ Wout)
{
    int j = blockIdx.x;   // 0..79
    __nv_bfloat162* dst = (__nv_bfloat162*)(d_WoutBf + (size_t)j * EDIM);
    if (j < NTAG) {
        float4 v = ((const float4*)(Wout + (size_t)j * EDIM))[threadIdx.x];
        dst[threadIdx.x * 2 + 0] = __floats2bfloat162_rn(v.x, v.y);
        dst[threadIdx.x * 2 + 1] = __floats2bfloat162_rn(v.z, v.w);
    } else {
        dst[threadIdx.x * 2 + 0] = __floats2bfloat162_rn(0.f, 0.f);
        dst[threadIdx.x * 2 + 1] = __floats2bfloat162_rn(0.f, 0.f);
    }
}

// ---------------- gather + convert embeddings ----------------
__global__ void k_gatherA(const int* __restrict__ ids, const float* __restrict__ embed)
{
    int r = blockIdx.x;                                   // 0..32767, r = s*256 + b
    int id = ids[(r & 255) * SEQ + (r >> 8)];             // input_ids[b*S + s]
    float4 v = ((const float4*)(embed + (size_t)id * EDIM))[threadIdx.x];
    __nv_bfloat162* dst = (__nv_bfloat162*)(d_Abf + (size_t)r * EDIM);
    dst[threadIdx.x * 2 + 0] = __floats2bfloat162_rn(v.x, v.y);
    dst[threadIdx.x * 2 + 1] = __floats2bfloat162_rn(v.z, v.w);
}

// ---------------- Z = A @ W^T + bias via mma.sync bf16 ----------------
// grid (16 jtiles, 256 mtiles). CTA: 128x128, 8 warps. 2 CTAs/SM (reg cap 128).
__global__ void __launch_bounds__(256, 2) k_zmma()
{
    __shared__ __nv_bfloat16 A_s[2][128][40];
    __shared__ __nv_bfloat16 B_s[2][128][40];
    __shared__ float bias_s[128];

    int tid = threadIdx.x;
    int lane = tid & 31, wid = tid >> 5;
    int warp_m = wid >> 1, warp_n = wid & 1;
    int jt = blockIdx.x, mt = blockIdx.y;
    int r0 = mt * 128, j0 = jt * 128;

    if (tid < 128) bias_s[tid] = d_biasZ[j0 + tid];

    unsigned As0 = smem_u32(&A_s[0][0][0]);
    unsigned Bs0 = smem_u32(&B_s[0][0][0]);
    const unsigned BUFB = 128 * 40 * 2;

    int q0 = tid, q1 = tid + 256;
    int rowA0 = q0 >> 2, c0 = (q0 & 3) * 8;
    int rowA1 = q1 >> 2, c1 = (q1 & 3) * 8;
    unsigned dA0 = (unsigned)(rowA0 * 40 + c0) * 2;
    unsigned dA1 = (unsigned)(rowA1 * 40 + c1) * 2;

    const __nv_bfloat16* Ag = d_Abf + (size_t)r0 * EDIM;
    const __nv_bfloat16* Bg = d_Wbf + (size_t)j0 * EDIM;

    unsigned aoff = (unsigned)((warp_m * 32 + (lane & 15)) * 40 + (lane >> 4) * 8);
    unsigned boff = (unsigned)((warp_n * 64 + (lane & 7) + (lane >> 4) * 8) * 40
                               + ((lane >> 3) & 1) * 8);

    float acc[2][8][4];
    #pragma unroll
    for (int mf = 0; mf < 2; mf++)
        #pragma unroll
        for (int j = 0; j < 8; j++)
            #pragma unroll
            for (int q = 0; q < 4; q++) acc[mf][j][q] = 0.f;

    {
        cpasync16(As0 + dA0, Ag + (size_t)rowA0 * EDIM + c0);
        cpasync16(As0 + dA1, Ag + (size_t)rowA1 * EDIM + c1);
        cpasync16(Bs0 + dA0, Bg + (size_t)rowA0 * EDIM + c0);
        cpasync16(Bs0 + dA1, Bg + (size_t)rowA1 * EDIM + c1);
        CP_COMMIT();
    }

    for (int kc = 0; kc < 16; kc++) {
        int buf = kc & 1;
        if (kc < 15) {
            int nb = (kc + 1) & 1;
            int ko = (kc + 1) * 32;
            cpasync16(As0 + nb * BUFB + dA0, Ag + (size_t)rowA0 * EDIM + ko + c0);
            cpasync16(As0 + nb * BUFB + dA1, Ag + (size_t)rowA1 * EDIM + ko + c1);
            cpasync16(Bs0 + nb * BUFB + dA0, Bg + (size_t)rowA0 * EDIM + ko + c0);
            cpasync16(Bs0 + nb * BUFB + dA1, Bg + (size_t)rowA1 * EDIM + ko + c1);
            CP_COMMIT();
            CP_WAIT(1);
        } else {
            CP_WAIT(0);
        }
        __syncthreads();

        unsigned Ab = As0 + buf * BUFB;
        unsigned Bb = Bs0 + buf * BUFB;
        #pragma unroll
        for (int kk = 0; kk < 2; kk++) {
            unsigned af[2][4];
            unsigned bfr[4][4];
            #pragma unroll
            for (int f = 0; f < 2; f++)
                ldsm4(af[f][0], af[f][1], af[f][2], af[f][3],
                      Ab + (aoff + f * 640 + kk * 16) * 2);
            #pragma unroll
            for (int g = 0; g < 4; g++)
                ldsm4(bfr[g][0], bfr[g][1], bfr[g][2], bfr[g][3],
                      Bb + (boff + g * 640 + kk * 16) * 2);
            #pragma unroll
            for (int mf = 0; mf < 2; mf++)
                #pragma unroll
                for (int j = 0; j < 8; j++) {
                    unsigned bb[2] = { bfr[j >> 1][(j & 1) * 2], bfr[j >> 1][(j & 1) * 2 + 1] };
                    mma16816(acc[mf][j], af[mf], bb);
                }
        }
        __syncthreads();
    }

    float* Zbase = (j0 < 1024) ? d_Zf : d_Zb;
    int jc0 = (j0 < 1024) ? j0 : (j0 - 1024);
    #pragma unroll
    for (int mf = 0; mf < 2; mf++) {
        int r = r0 + warp_m * 32 + mf * 16 + (lane >> 2);
        #pragma unroll
        for (int j = 0; j < 8; j++) {
            int cl = warp_n * 64 + j * 8 + (lane & 3) * 2;
            float2 v0 = { acc[mf][j][0] + bias_s[cl], acc[mf][j][1] + bias_s[cl + 1] };
            float2 v1 = { acc[mf][j][2] + bias_s[cl], acc[mf][j][3] + bias_s[cl + 1] };
            *(float2*)(Zbase + (size_t)r * G4 + jc0 + cl) = v0;
            *(float2*)(Zbase + (size_t)(r + 8) * G4 + jc0 + cl) = v1;
        }
    }
}

// ---------------- persistent tensor-core recurrence, cluster-synced ----------------
// 128 blocks x 128 threads, clusters of 16 (one per dir+btile).
// Split barrier: h stores -> arrive -> Z prefetch -> wait (prefetch latency
// hides inside the wait window; arrival released ~epilogue earlier for peers).
__global__ void __launch_bounds__(128, 1) __cluster_dims__(16, 1, 1) k_recurrent(
    const float* __restrict__ Whf, const float* __restrict__ Whb,
    const float* __restrict__ c0)
{
    extern __shared__ __nv_bfloat16 sm_rec[];
    __nv_bfloat16* Wsb = sm_rec;              // [64 j][WST], j = g*16 + hul
    __nv_bfloat16* Hsm = sm_rec + 64 * WST;   // [64 b][WST]

    int bid = blockIdx.x;
    int dir = bid >> 6;
    int b0  = ((bid >> 4) & 3) * 64;
    int hu0 = (bid & 15) * 16;
    int tid = threadIdx.x;
    int lane = tid & 31, warp = tid >> 5;

    const float* Whh = dir ? Whb : Whf;
    const float* Z   = dir ? d_Zb : d_Zf;

    // ---- load + convert W slice once: Wsb[j][k], j = g*16 + hu_local ----
    {
        int j = tid >> 1;                       // 0..63
        int kh = (tid & 1) * 128;               // k half
        int g = j >> 4, hul = j & 15;
        const float4* src = (const float4*)(Whh + (size_t)(g * 256 + hu0 + hul) * HD + kh);
        __nv_bfloat162* dst = (__nv_bfloat162*)(Wsb + j * WST + kh);
        #pragma unroll
        for (int q = 0; q < 32; q++) {
            float4 v = src[q];
            dst[q * 2 + 0] = __floats2bfloat162_rn(v.x, v.y);
            dst[q * 2 + 1] = __floats2bfloat162_rn(v.z, v.w);
        }
    }

    int bbase = b0 + warp * 16 + (lane >> 2);
    int hbase = (lane & 3) * 2;

    float creg[2][2][2];   // [rs][hh][hp]
    #pragma unroll
    for (int rs = 0; rs < 2; rs++)
        #pragma unroll
        for (int hh = 0; hh < 2; hh++) {
            float2 cv = *(const float2*)(c0 + (size_t)dir * 65536
                          + (size_t)(bbase + rs * 8) * HD + hu0 + hh * 8 + hbase);
            creg[rs][hh][0] = cv.x;
            creg[rs][hh][1] = cv.y;
        }

    unsigned HsmB = smem_u32(Hsm);
    unsigned WsbB = smem_u32(Wsb);
    unsigned aoff = HsmB + (unsigned)((warp * 16 + (lane & 15)) * WST + (lane >> 4) * 8) * 2;
    unsigned boff = WsbB + (unsigned)(((lane & 7) + ((lane >> 4) * 8)) * WST
                                      + ((lane >> 3) & 1) * 8) * 2;

    // ---- prefetch Z for step 0 into registers ----
    float zreg[8][4];
    {
        int s0 = dir ? (SEQ - 1) : 0;
        const float* zp0 = Z + (size_t)(s0 * BATCH + bbase) * G4;
        #pragma unroll
        for (int f = 0; f < 8; f++) {
            int col = (f >> 1) * 256 + hu0 + (f & 1) * 8 + hbase;
            float2 v0 = *(const float2*)(zp0 + col);
            float2 v1 = *(const float2*)(zp0 + 8 * G4 + col);
            zreg[f][0] = v0.x; zreg[f][1] = v0.y; zreg[f][2] = v1.x; zreg[f][3] = v1.y;
        }
    }

    __syncthreads();
    CLUSTER_ARRIVE();   // h0 ping buffer + all peers' W ready
    CLUSTER_WAIT();

    for (int t = 0; t < SEQ; t++) {
        int s = dir ? (SEQ - 1 - t) : t;
        const __nv_bfloat16* hsrc = d_Hbf + (size_t)((t & 1) * 2 + dir) * 65536;
        __nv_bfloat16*       hdst = d_Hbf + (size_t)(((t + 1) & 1) * 2 + dir) * 65536;

        // cp.async h_prev tile (64 rows x 256 k bf16)
        #pragma unroll
        for (int i = 0; i < 16; i++) {
            int ch = tid + i * 128;
            int row = ch >> 5, ko = (ch & 31) * 8;
            cpasync16(HsmB + (unsigned)(row * WST + ko) * 2,
                      hsrc + (size_t)(b0 + row) * HD + ko);
        }
        CP_COMMIT();

        // acc from prefetched Z registers (no memory on critical path)
        float acc[8][4];
        #pragma unroll
        for (int f = 0; f < 8; f++)
            #pragma unroll
            for (int q = 0; q < 4; q++) acc[f][q] = zreg[f][q];

        CP_WAIT(0);
        __syncthreads();

        #pragma unroll
        for (int kk = 0; kk < 16; kk++) {
            unsigned a[4];
            ldsm4(a[0], a[1], a[2], a[3], aoff + kk * 32);
            unsigned bq[4][4];
            #pragma unroll
            for (int g2 = 0; g2 < 4; g2++)
                ldsm4(bq[g2][0], bq[g2][1], bq[g2][2], bq[g2][3],
                      boff + g2 * (16 * WST * 2) + kk * 32);
            #pragma unroll
            for (int f = 0; f < 8; f++) {
                unsigned bb[2] = { bq[f >> 1][(f & 1) * 2], bq[f >> 1][(f & 1) * 2 + 1] };
                mma16816(acc[f], a, bb);
            }
        }

        // gates + cell update (HW tanh); h -> ping (bf16) + fused feats (bf16)
        #pragma unroll
        for (int rs = 0; rs < 2; rs++) {
            int b = bbase + rs * 8;
            #pragma unroll
            for (int hh = 0; hh < 2; hh++) {
                int hu = hu0 + hh * 8 + hbase;
                float h0v = 0.f, h1v = 0.f;
                #pragma unroll
                for (int hp = 0; hp < 2; hp++) {
                    int q = rs * 2 + hp;
                    float zi = acc[0 + hh][q];
                    float zf = acc[2 + hh][q];
                    float zg = acc[4 + hh][q];
                    float zo = acc[6 + hh][q];
                    float cv = sigma(zf) * creg[rs][hh][hp] + sigma(zi) * tanha(zg);
                    float h  = sigma(zo) * tanha(cv);
                    creg[rs][hh][hp] = cv;
                    if (hp) h1v = h; else h0v = h;
                }
                __nv_bfloat162 hb = __floats2bfloat162_rn(h0v, h1v);
                *(__nv_bfloat162*)(hdst + (size_t)b * HD + hu) = hb;
                *(__nv_bfloat162*)(d_Hh + (size_t)(s * BATCH + b) * 512 + dir * 256 + hu) = hb;
            }
        }

        // release h stores to peers as early as possible
        CLUSTER_ARRIVE();

        // prefetch Z for t+1 (DRAM latency hides inside the barrier wait)
        if (t + 1 < SEQ) {
            int sn = dir ? (SEQ - 2 - t) : (t + 1);
            const float* zpn = Z + (size_t)(sn * BATCH + bbase) * G4;
            #pragma unroll
            for (int f = 0; f < 8; f++) {
                int col = (f >> 1) * 256 + hu0 + (f & 1) * 8 + hbase;
                float2 v0 = *(const float2*)(zpn + col);
                float2 v1 = *(const float2*)(zpn + 8 * G4 + col);
                zreg[f][0] = v0.x; zreg[f][1] = v0.y; zreg[f][2] = v1.x; zreg[f][3] = v1.y;
            }
        }

        CLUSTER_WAIT();   // acquire peers' h
    }
}

// ---------------- em = Hh @ Wout^T + b_out via mma.sync bf16 ----------------
__global__ void __launch_bounds__(256, 1) k_emis(const float* __restrict__ bout)
{
    extern __shared__ char sme[];
    __nv_bfloat16* Bs = (__nv_bfloat16*)sme;              // [80][BST]
    __nv_bfloat16* As = (__nv_bfloat16*)(sme + 83200);    // [2][128][40]
    float* bias_s = (float*)(sme + 83200 + 20480);        // [80]

    int tid = threadIdx.x, lane = tid & 31, warp = tid >> 5;
    int r0 = blockIdx.x * 128;

    if (tid < 80) bias_s[tid] = (tid < NTAG) ? bout[tid] : 0.f;

    unsigned BsB = smem_u32(Bs), AsB = smem_u32(As);

    #pragma unroll
    for (int i = 0; i < 20; i++) {
        int ch = tid + i * 256;            // 0..5119
        int j = ch >> 6, ko = (ch & 63) * 8;
        cpasync16(BsB + (unsigned)(j * BST + ko) * 2, d_WoutBf + (size_t)j * EDIM + ko);
    }
    #pragma unroll
    for (int i = 0; i < 2; i++) {
        int ch = tid + i * 256;            // 0..511
        int row = ch >> 2, ko = (ch & 3) * 8;
        cpasync16(AsB + (unsigned)(row * 40 + ko) * 2,
                  d_Hh + (size_t)(r0 + row) * 512 + ko);
    }
    CP_COMMIT();

    float acc[10][4];
    #pragma unroll
    for (int f = 0; f < 10; f++)
        #pragma unroll
        for (int q = 0; q < 4; q++) acc[f][q] = 0.f;

    unsigned aoffE = AsB + (unsigned)((warp * 16 + (lane & 15)) * 40 + (lane >> 4) * 8) * 2;
    unsigned boffE = BsB + (unsigned)(((lane & 7) + ((lane >> 4) * 8)) * BST
                                      + ((lane >> 3) & 1) * 8) * 2;

    for (int kc = 0; kc < 16; kc++) {
        int buf = kc & 1;
        if (kc < 15) {
            int nb = (kc + 1) & 1;
            #pragma unroll
            for (int i = 0; i < 2; i++) {
                int ch = tid + i * 256;
                int row = ch >> 2, ko = (ch & 3) * 8;
                cpasync16(AsB + (unsigned)(nb * 5120 + row * 40 + ko) * 2,
                          d_Hh + (size_t)(r0 + row) * 512 + (kc + 1) * 32 + ko);
            }
            CP_COMMIT();
            CP_WAIT(1);
        } else {
            CP_WAIT(0);
        }
        __syncthreads();

        #pragma unroll
        for (int kk = 0; kk < 2; kk++) {
            unsigned a[4];
            ldsm4(a[0], a[1], a[2], a[3], aoffE + (unsigned)(buf * 5120) * 2 + kk * 32);
            unsigned bq[5][4];
            #pragma unroll
            for (int p = 0; p < 5; p++)
                ldsm4(bq[p][0], bq[p][1], bq[p][2], bq[p][3],
                      boffE + (unsigned)(p * 16 * BST + kc * 32 + kk * 16) * 2);
            #pragma unroll
            for (int f = 0; f < 10; f++) {
                unsigned bb[2] = { bq[f >> 1][(f & 1) * 2], bq[f >> 1][(f & 1) * 2 + 1] };
                mma16816(acc[f], a, bb);
            }
        }
        __syncthreads();
    }

    #pragma unroll
    for (int f = 0; f < 10; f++) {
        int colb = f * 8 + (lane & 3) * 2;
        #pragma unroll
        for (int q = 0; q < 4; q++) {
            int cc = colb + (q & 1);
            if (cc < NTAG) {
                int r = r0 + warp * 16 + (lane >> 2) + (q >> 1) * 8;
                d_em[(size_t)r * NTAG + cc] = acc[f][q] + bias_s[cc];
            }
        }
    }
}

// ---------------- CRF: 2 batch elements per block, named-barrier halves ----------------
__global__ void __launch_bounds__(256) k_crf(
    const int* __restrict__ tag_ids, const int* __restrict__ lengths,
    const float* __restrict__ start, const float* __restrict__ endt,
    const float* __restrict__ trans)
{
    __shared__ float E[NTAG * NTAG];
    __shared__ float alpha[2][128];
    __shared__ float p[2][128];
    __shared__ float red[2][128];
    int tid = threadIdx.x;
    int half = tid >> 7;          // 0 or 1
    int ltid = tid & 127;
    int b = blockIdx.x * 2 + half;
    int bar = 1 + half;           // named barrier id per half
    int len = lengths[b];

    for (int i = tid; i < NTAG * NTAG; i += 256) E[i] = __expf(trans[i]);

    float part = 0.f;
    if (ltid >= 1 && ltid < len) {
        int tg = tag_ids[b * SEQ + ltid];
        int pv = tag_ids[b * SEQ + ltid - 1];
        part = trans[pv * NTAG + tg] + d_em[(size_t)(ltid * BATCH + b) * NTAG + tg];
    }
    if (ltid == 0) {
        int t0 = tag_ids[b * SEQ];
        part += start[t0] + d_em[(size_t)b * NTAG + t0];
        part += endt[tag_ids[b * SEQ + len - 1]];
    }
    red[half][ltid] = part;
    alpha[half][ltid] = (ltid < NTAG) ? start[ltid] + d_em[(size_t)b * NTAG + ltid] : 0.f;
    __syncthreads();   // E table + both halves' init complete (uniform, executed once)

    for (int s2 = 64; s2 > 0; s2 >>= 1) {
        if (ltid < s2) red[half][ltid] += red[half][ltid + s2];
        NB_SYNC(bar);
    }
    float score = red[half][0];

    for (int t = 1; t < len; t++) {
        float m = alpha[half][0];
        p[half][ltid] = (ltid < NTAG) ? __expf(alpha[half][ltid] - m) : 0.f;
        NB_SYNC(bar);
        if (ltid < NTAG) {
            float s0 = 0.f, s1 = 0.f, s2 = 0.f, s3 = 0.f;
            const float* ph = p[half];
            #pragma unroll
            for (int i = 0; i < NTAG; i += 4) {
                s0 = fmaf(ph[i],     E[(i)     * NTAG + ltid], s0);
                s1 = fmaf(ph[i + 1], E[(i + 1) * NTAG + ltid], s1);
                s2 = fmaf(ph[i + 2], E[(i + 2) * NTAG + ltid], s2);
                s3 = fmaf(ph[i + 3], E[(i + 3) * NTAG + ltid], s3);
            }
            alpha[half][ltid] = m + __logf((s0 + s1) + (s2 + s3))
                                + d_em[(size_t)(t * BATCH + b) * NTAG + ltid];
        }
        NB_SYNC(bar);
    }

    float m = alpha[half][0] + endt[0];
    p[half][ltid] = (ltid < NTAG) ? __expf(alpha[half][ltid] + endt[ltid] - m) : 0.f;
    NB_SYNC(bar);
    for (int s2 = 64; s2 > 0; s2 >>= 1) {
        if (ltid < s2) p[half][ltid] += p[half][ltid + s2];
        NB_SYNC(bar);
    }
    if (ltid == 0) d_llh[b] = score - (m + __logf(p[half][0]));
}

// ---------------- final reduce: out = -mean(llh) ----------------
__global__ void k_reduce(float* __restrict__ out)
{
    __shared__ float red[256];
    int tid = threadIdx.x;
    red[tid] = d_llh[tid];
    __syncthreads();
    for (int s = 128; s > 0; s >>= 1) {
        if (tid < s) red[tid] += red[tid + s];
        __syncthreads();
    }
    if (tid == 0) out[0] = -red[0] / 256.f;
}

extern "C" void kernel_launch(void* const* d_in, const int* in_sizes, int n_in,
                              void* d_out, int out_size)
{
    const int*   ids   = (const int*)d_in[0];
    const int*   tags  = (const int*)d_in[1];
    const int*   lens  = (const int*)d_in[2];
    const float* embed = (const float*)d_in[3];
    const float* Wihf  = (const float*)d_in[4];
    const float* Whhf  = (const float*)d_in[5];
    const float* bihf  = (const float*)d_in[6];
    const float* bhhf  = (const float*)d_in[7];
    const float* Wihb  = (const float*)d_in[8];
    const float* Whhb  = (const float*)d_in[9];
    const float* bihb  = (const float*)d_in[10];
    const float* bhhb  = (const float*)d_in[11];
    const float* Wout  = (const float*)d_in[12];
    const float* bout  = (const float*)d_in[13];
    const float* start = (const float*)d_in[14];
    const float* endt  = (const float*)d_in[15];
    const float* trans = (const float*)d_in[16];
    const float* h0    = (const float*)d_in[17];
    const float* c0    = (const float*)d_in[18];
    float* out = (float*)d_out;

    const int RSMEM = 128 * WST * 2;              // Wsb(64) + Hsm(64) rows, bf16
    const int ESMEM = 83200 + 20480 + 320;        // Bs + As + bias
    cudaFuncSetAttribute(k_recurrent, cudaFuncAttributeMaxDynamicSharedMemorySize, RSMEM);
    cudaFuncSetAttribute(k_recurrent, cudaFuncAttributeNonPortableClusterSizeAllowed, 1);
    cudaFuncSetAttribute(k_emis, cudaFuncAttributeMaxDynamicSharedMemorySize, ESMEM);

    k_init<<<512, 256>>>(h0);
    k_convW<<<2048, 128>>>(Wihf, Wihb, bihf, bhhf, bihb, bhhb);
    k_convO<<<80, 128>>>(Wout);
    k_gatherA<<<MROWS, 128>>>(ids, embed);
    k_zmma<<<dim3(16, 256), 256>>>();
    k_recurrent<<<128, 128, RSMEM>>>(Whhf, Whhb, c0);
    k_emis<<<256, 256, ESMEM>>>(bout);
    k_crf<<<128, 256>>>(tags, lens, start, endt, trans);
    k_reduce<<<1, 256>>>(out);
}

// round 15
// speedup vs baseline: 1.0879x; 1.0879x over previous
#include <cuda_runtime.h>
#include <cuda_bf16.h>

#define BATCH 256
#define SEQ   128
#define EDIM  512
#define HD    256
#define G4    1024
#define NTAG  76
#define MROWS 32768   // SEQ*BATCH
#define WST   264     // recurrence smem row stride (bf16), conflict-free ldmatrix
#define BST   520     // emis B smem row stride (bf16)

// ---------------- scratch (device globals; no runtime allocation) ----------------
__device__ float d_Zf[(size_t)MROWS * G4];   // input proj fwd, (S,B,4HD), gate order i,f,g,o
__device__ float d_Zb[(size_t)MROWS * G4];   // input proj bwd
__device__ float d_em[(size_t)MROWS * NTAG]; // emissions (S,B,T)
__device__ float d_llh[BATCH];

__device__ __align__(16) __nv_bfloat16 d_Hh[(size_t)MROWS * 512];  // feats bf16: [r][hf|hb]
__device__ __align__(16) __nv_bfloat16 d_Hbf[2 * 2 * BATCH * HD];  // ping [parity][dir][b][hu]
__device__ __align__(16) __nv_bfloat16 d_Abf[(size_t)MROWS * EDIM]; // gathered embeddings
__device__ __align__(16) __nv_bfloat16 d_Wbf[(size_t)2048 * EDIM];  // [Wf;Wb] bf16
__device__ __align__(16) __nv_bfloat16 d_WoutBf[80 * EDIM];         // Wout bf16, padded 80 rows
__device__ float d_biasZ[2048];                                     // b_ih+b_hh both dirs

__device__ __forceinline__ float sigm(float x)  { return 1.0f / (1.0f + __expf(-x)); }
// fast HW gates (recurrence only): tanh.approx + sigmoid via tanh identity
__device__ __forceinline__ float tanha(float x) {
    float y; asm("tanh.approx.f32 %0, %1;" : "=f"(y) : "f"(x)); return y;
}
__device__ __forceinline__ float sigma(float x) { return fmaf(tanha(x * 0.5f), 0.5f, 0.5f); }

// ================= baseline-PTX tensor helpers (no sm_103a-gated instrs) =================
__device__ __forceinline__ unsigned smem_u32(const void* p) {
    unsigned a;
    asm("{ .reg .u64 t; cvta.to.shared.u64 t, %1; cvt.u32.u64 %0, t; }" : "=r"(a) : "l"(p));
    return a;
}
__device__ __forceinline__ void ldsm4(unsigned& r0, unsigned& r1, unsigned& r2, unsigned& r3,
                                      unsigned addr) {
    asm volatile("ldmatrix.sync.aligned.m8n8.x4.shared.b16 {%0,%1,%2,%3}, [%4];"
                 : "=r"(r0), "=r"(r1), "=r"(r2), "=r"(r3) : "r"(addr));
}
__device__ __forceinline__ void mma16816(float* d, const unsigned* a, const unsigned* b) {
    asm volatile(
        "mma.sync.aligned.m16n8k16.row.col.f32.bf16.bf16.f32 "
        "{%0,%1,%2,%3}, {%4,%5,%6,%7}, {%8,%9}, {%0,%1,%2,%3};"
        : "+f"(d[0]), "+f"(d[1]), "+f"(d[2]), "+f"(d[3])
        : "r"(a[0]), "r"(a[1]), "r"(a[2]), "r"(a[3]), "r"(b[0]), "r"(b[1]));
}
__device__ __forceinline__ void cpasync16(unsigned dst, const void* src) {
    asm volatile("cp.async.cg.shared.global [%0], [%1], 16;" :: "r"(dst), "l"(src));
}
#define CP_COMMIT() asm volatile("cp.async.commit_group;" ::: "memory")
#define CP_WAIT(n)  asm volatile("cp.async.wait_group %0;" :: "n"(n) : "memory")
#define CLUSTER_SYNC() do { \
    asm volatile("barrier.cluster.arrive.aligned;" ::: "memory"); \
    asm volatile("barrier.cluster.wait.aligned;" ::: "memory"); \
} while (0)

// ---------------- init: h0 -> bf16 ping parity 0 ----------------
__global__ void k_init(const float* __restrict__ h0)
{
    int i = blockIdx.x * 256 + threadIdx.x;   // grid 512 -> 131072 exact
    d_Hbf[i] = __float2bfloat16(h0[i]);
}

// ---------------- convert weights + bias ----------------
__global__ void k_convW(const float* __restrict__ Wf, const float* __restrict__ Wb,
                        const float* __restrict__ bihf, const float* __restrict__ bhhf,
                        const float* __restrict__ bihb, const float* __restrict__ bhhb)
{
    int j = blockIdx.x;   // 0..2047
    const float* src = (j < 1024) ? (Wf + (size_t)j * EDIM) : (Wb + (size_t)(j - 1024) * EDIM);
    float4 v = ((const float4*)src)[threadIdx.x];   // 128 threads * 4 = 512
    __nv_bfloat162* dst = (__nv_bfloat162*)(d_Wbf + (size_t)j * EDIM);
    dst[threadIdx.x * 2 + 0] = __floats2bfloat162_rn(v.x, v.y);
    dst[threadIdx.x * 2 + 1] = __floats2bfloat162_rn(v.z, v.w);
    if (threadIdx.x == 0)
        d_biasZ[j] = (j < 1024) ? (bihf[j] + bhhf[j]) : (bihb[j - 1024] + bhhb[j - 1024]);
}

__global__ void k_convO(const float* __restrict__ Wout)
{
    int j = blockIdx.x;   // 0..79
    __nv_bfloat162* dst = (__nv_bfloat162*)(d_WoutBf + (size_t)j * EDIM);
    if (j < NTAG) {
        float4 v = ((const float4*)(Wout + (size_t)j * EDIM))[threadIdx.x];
        dst[threadIdx.x * 2 + 0] = __floats2bfloat162_rn(v.x, v.y);
        dst[threadIdx.x * 2 + 1] = __floats2bfloat162_rn(v.z, v.w);
    } else {
        dst[threadIdx.x * 2 + 0] = __floats2bfloat162_rn(0.f, 0.f);
        dst[threadIdx.x * 2 + 1] = __floats2bfloat162_rn(0.f, 0.f);
    }
}

// ---------------- gather + convert embeddings ----------------
__global__ void k_gatherA(const int* __restrict__ ids, const float* __restrict__ embed)
{
    int r = blockIdx.x;                                   // 0..32767, r = s*256 + b
    int id = ids[(r & 255) * SEQ + (r >> 8)];             // input_ids[b*S + s]
    float4 v = ((const float4*)(embed + (size_t)id * EDIM))[threadIdx.x];
    __nv_bfloat162* dst = (__nv_bfloat162*)(d_Abf + (size_t)r * EDIM);
    dst[threadIdx.x * 2 + 0] = __floats2bfloat162_rn(v.x, v.y);
    dst[threadIdx.x * 2 + 1] = __floats2bfloat162_rn(v.z, v.w);
}

// ---------------- Z = A @ W^T + bias via mma.sync bf16, 3-stage pipeline ----------------
// grid (16 jtiles, 256 mtiles). CTA: 128x128, 8 warps. 2 CTAs/SM (reg cap 128).
// 3 smem stages: each cp.async group gets ~2 compute blocks of latency cover.
__global__ void __launch_bounds__(256, 2) k_zmma()
{
    extern __shared__ char smz[];
    const unsigned BUFB = 128 * 40 * 2;                 // 10240 bytes per matrix stage
    __nv_bfloat16* A_s = (__nv_bfloat16*)smz;           // [3][128][40]
    __nv_bfloat16* B_s = (__nv_bfloat16*)(smz + 3 * BUFB);
    float* bias_s = (float*)(smz + 6 * BUFB);           // [128]

    int tid = threadIdx.x;
    int lane = tid & 31, wid = tid >> 5;
    int warp_m = wid >> 1, warp_n = wid & 1;
    int jt = blockIdx.x, mt = blockIdx.y;
    int r0 = mt * 128, j0 = jt * 128;

    if (tid < 128) bias_s[tid] = d_biasZ[j0 + tid];

    unsigned As0 = smem_u32(A_s);
    unsigned Bs0 = smem_u32(B_s);

    int q0 = tid, q1 = tid + 256;
    int rowA0 = q0 >> 2, c0 = (q0 & 3) * 8;
    int rowA1 = q1 >> 2, c1 = (q1 & 3) * 8;
    unsigned dA0 = (unsigned)(rowA0 * 40 + c0) * 2;
    unsigned dA1 = (unsigned)(rowA1 * 40 + c1) * 2;

    const __nv_bfloat16* Ag = d_Abf + (size_t)r0 * EDIM;
    const __nv_bfloat16* Bg = d_Wbf + (size_t)j0 * EDIM;

    unsigned aoff = (unsigned)((warp_m * 32 + (lane & 15)) * 40 + (lane >> 4) * 8);
    unsigned boff = (unsigned)((warp_n * 64 + (lane & 7) + (lane >> 4) * 8) * 40
                               + ((lane >> 3) & 1) * 8);

    float acc[2][8][4];
    #pragma unroll
    for (int mf = 0; mf < 2; mf++)
        #pragma unroll
        for (int j = 0; j < 8; j++)
            #pragma unroll
            for (int q = 0; q < 4; q++) acc[mf][j][q] = 0.f;

    // prefetch stages 0 and 1
    #pragma unroll
    for (int pk = 0; pk < 2; pk++) {
        int ko = pk * 32;
        cpasync16(As0 + pk * BUFB + dA0, Ag + (size_t)rowA0 * EDIM + ko + c0);
        cpasync16(As0 + pk * BUFB + dA1, Ag + (size_t)rowA1 * EDIM + ko + c1);
        cpasync16(Bs0 + pk * BUFB + dA0, Bg + (size_t)rowA0 * EDIM + ko + c0);
        cpasync16(Bs0 + pk * BUFB + dA1, Bg + (size_t)rowA1 * EDIM + ko + c1);
        CP_COMMIT();
    }

    for (int kc = 0; kc < 16; kc++) {
        if (kc < 15) { CP_WAIT(1); } else { CP_WAIT(0); }
        __syncthreads();

        // prefetch stage kc+2 (overwrites buffer (kc-1)%3, drained by syncthreads)
        if (kc + 2 < 16) {
            int nb = (kc + 2) % 3;
            int ko = (kc + 2) * 32;
            cpasync16(As0 + nb * BUFB + dA0, Ag + (size_t)rowA0 * EDIM + ko + c0);
            cpasync16(As0 + nb * BUFB + dA1, Ag + (size_t)rowA1 * EDIM + ko + c1);
            cpasync16(Bs0 + nb * BUFB + dA0, Bg + (size_t)rowA0 * EDIM + ko + c0);
            cpasync16(Bs0 + nb * BUFB + dA1, Bg + (size_t)rowA1 * EDIM + ko + c1);
            CP_COMMIT();
        }

        int buf = kc % 3;
        unsigned Ab = As0 + buf * BUFB;
        unsigned Bb = Bs0 + buf * BUFB;
        #pragma unroll
        for (int kk = 0; kk < 2; kk++) {
            unsigned af[2][4];
            unsigned bfr[4][4];
            #pragma unroll
            for (int f = 0; f < 2; f++)
                ldsm4(af[f][0], af[f][1], af[f][2], af[f][3],
                      Ab + (aoff + f * 640 + kk * 16) * 2);
            #pragma unroll
            for (int g = 0; g < 4; g++)
                ldsm4(bfr[g][0], bfr[g][1], bfr[g][2], bfr[g][3],
                      Bb + (boff + g * 640 + kk * 16) * 2);
            #pragma unroll
            for (int mf = 0; mf < 2; mf++)
                #pragma unroll
                for (int j = 0; j < 8; j++) {
                    unsigned bb[2] = { bfr[j >> 1][(j & 1) * 2], bfr[j >> 1][(j & 1) * 2 + 1] };
                    mma16816(acc[mf][j], af[mf], bb);
                }
        }
    }

    float* Zbase = (j0 < 1024) ? d_Zf : d_Zb;
    int jc0 = (j0 < 1024) ? j0 : (j0 - 1024);
    #pragma unroll
    for (int mf = 0; mf < 2; mf++) {
        int r = r0 + warp_m * 32 + mf * 16 + (lane >> 2);
        #pragma unroll
        for (int j = 0; j < 8; j++) {
            int cl = warp_n * 64 + j * 8 + (lane & 3) * 2;
            float2 v0 = { acc[mf][j][0] + bias_s[cl], acc[mf][j][1] + bias_s[cl + 1] };
            float2 v1 = { acc[mf][j][2] + bias_s[cl], acc[mf][j][3] + bias_s[cl + 1] };
            *(float2*)(Zbase + (size_t)r * G4 + jc0 + cl) = v0;
            *(float2*)(Zbase + (size_t)(r + 8) * G4 + jc0 + cl) = v1;
        }
    }
}

// ---------------- persistent tensor-core recurrence, cluster-synced (R13) ----------------
__global__ void __launch_bounds__(128, 1) __cluster_dims__(16, 1, 1) k_recurrent(
    const float* __restrict__ Whf, const float* __restrict__ Whb,
    const float* __restrict__ c0)
{
    extern __shared__ __nv_bfloat16 sm_rec[];
    __nv_bfloat16* Wsb = sm_rec;              // [64 j][WST], j = g*16 + hul
    __nv_bfloat16* Hsm = sm_rec + 64 * WST;   // [64 b][WST]

    int bid = blockIdx.x;
    int dir = bid >> 6;
    int b0  = ((bid >> 4) & 3) * 64;
    int hu0 = (bid & 15) * 16;
    int tid = threadIdx.x;
    int lane = tid & 31, warp = tid >> 5;

    const float* Whh = dir ? Whb : Whf;
    const float* Z   = dir ? d_Zb : d_Zf;

    {
        int j = tid >> 1;
        int kh = (tid & 1) * 128;
        int g = j >> 4, hul = j & 15;
        const float4* src = (const float4*)(Whh + (size_t)(g * 256 + hu0 + hul) * HD + kh);
        __nv_bfloat162* dst = (__nv_bfloat162*)(Wsb + j * WST + kh);
        #pragma unroll
        for (int q = 0; q < 32; q++) {
            float4 v = src[q];
            dst[q * 2 + 0] = __floats2bfloat162_rn(v.x, v.y);
            dst[q * 2 + 1] = __floats2bfloat162_rn(v.z, v.w);
        }
    }

    int bbase = b0 + warp * 16 + (lane >> 2);
    int hbase = (lane & 3) * 2;

    float creg[2][2][2];
    #pragma unroll
    for (int rs = 0; rs < 2; rs++)
        #pragma unroll
        for (int hh = 0; hh < 2; hh++) {
            float2 cv = *(const float2*)(c0 + (size_t)dir * 65536
                          + (size_t)(bbase + rs * 8) * HD + hu0 + hh * 8 + hbase);
            creg[rs][hh][0] = cv.x;
            creg[rs][hh][1] = cv.y;
        }

    unsigned HsmB = smem_u32(Hsm);
    unsigned WsbB = smem_u32(Wsb);
    unsigned aoff = HsmB + (unsigned)((warp * 16 + (lane & 15)) * WST + (lane >> 4) * 8) * 2;
    unsigned boff = WsbB + (unsigned)(((lane & 7) + ((lane >> 4) * 8)) * WST
                                      + ((lane >> 3) & 1) * 8) * 2;

    float zreg[8][4];
    {
        int s0 = dir ? (SEQ - 1) : 0;
        const float* zp0 = Z + (size_t)(s0 * BATCH + bbase) * G4;
        #pragma unroll
        for (int f = 0; f < 8; f++) {
            int col = (f >> 1) * 256 + hu0 + (f & 1) * 8 + hbase;
            float2 v0 = *(const float2*)(zp0 + col);
            float2 v1 = *(const float2*)(zp0 + 8 * G4 + col);
            zreg[f][0] = v0.x; zreg[f][1] = v0.y; zreg[f][2] = v1.x; zreg[f][3] = v1.y;
        }
    }

    __syncthreads();
    CLUSTER_SYNC();   // h0 ping buffer + all peers' W ready

    for (int t = 0; t < SEQ; t++) {
        int s = dir ? (SEQ - 1 - t) : t;
        const __nv_bfloat16* hsrc = d_Hbf + (size_t)((t & 1) * 2 + dir) * 65536;
        __nv_bfloat16*       hdst = d_Hbf + (size_t)(((t + 1) & 1) * 2 + dir) * 65536;

        #pragma unroll
        for (int i = 0; i < 16; i++) {
            int ch = tid + i * 128;
            int row = ch >> 5, ko = (ch & 31) * 8;
            cpasync16(HsmB + (unsigned)(row * WST + ko) * 2,
                      hsrc + (size_t)(b0 + row) * HD + ko);
        }
        CP_COMMIT();

        float acc[8][4];
        #pragma unroll
        for (int f = 0; f < 8; f++)
            #pragma unroll
            for (int q = 0; q < 4; q++) acc[f][q] = zreg[f][q];

        CP_WAIT(0);
        __syncthreads();

        #pragma unroll
        for (int kk = 0; kk < 16; kk++) {
            unsigned a[4];
            ldsm4(a[0], a[1], a[2], a[3], aoff + kk * 32);
            unsigned bq[4][4];
            #pragma unroll
            for (int g2 = 0; g2 < 4; g2++)
                ldsm4(bq[g2][0], bq[g2][1], bq[g2][2], bq[g2][3],
                      boff + g2 * (16 * WST * 2) + kk * 32);
            #pragma unroll
            for (int f = 0; f < 8; f++) {
                unsigned bb[2] = { bq[f >> 1][(f & 1) * 2], bq[f >> 1][(f & 1) * 2 + 1] };
                mma16816(acc[f], a, bb);
            }
        }

        if (t + 1 < SEQ) {
            int sn = dir ? (SEQ - 2 - t) : (t + 1);
            const float* zpn = Z + (size_t)(sn * BATCH + bbase) * G4;
            #pragma unroll
            for (int f = 0; f < 8; f++) {
                int col = (f >> 1) * 256 + hu0 + (f & 1) * 8 + hbase;
                float2 v0 = *(const float2*)(zpn + col);
                float2 v1 = *(const float2*)(zpn + 8 * G4 + col);
                zreg[f][0] = v0.x; zreg[f][1] = v0.y; zreg[f][2] = v1.x; zreg[f][3] = v1.y;
            }
        }

        #pragma unroll
        for (int rs = 0; rs < 2; rs++) {
            int b = bbase + rs * 8;
            #pragma unroll
            for (int hh = 0; hh < 2; hh++) {
                int hu = hu0 + hh * 8 + hbase;
                float h0v = 0.f, h1v = 0.f;
                #pragma unroll
                for (int hp = 0; hp < 2; hp++) {
                    int q = rs * 2 + hp;
                    float zi = acc[0 + hh][q];
                    float zf = acc[2 + hh][q];
                    float zg = acc[4 + hh][q];
                    float zo = acc[6 + hh][q];
                    float cv = sigma(zf) * creg[rs][hh][hp] + sigma(zi) * tanha(zg);
                    float h  = sigma(zo) * tanha(cv);
                    creg[rs][hh][hp] = cv;
                    if (hp) h1v = h; else h0v = h;
                }
                __nv_bfloat162 hb = __floats2bfloat162_rn(h0v, h1v);
                *(__nv_bfloat162*)(hdst + (size_t)b * HD + hu) = hb;
                *(__nv_bfloat162*)(d_Hh + (size_t)(s * BATCH + b) * 512 + dir * 256 + hu) = hb;
            }
        }

        CLUSTER_SYNC();
    }
}

// ---------------- em = Hh @ Wout^T + b_out via mma.sync bf16 ----------------
__global__ void __launch_bounds__(256, 1) k_emis(const float* __restrict__ bout)
{
    extern __shared__ char sme[];
    __nv_bfloat16* Bs = (__nv_bfloat16*)sme;              // [80][BST]
    __nv_bfloat16* As = (__nv_bfloat16*)(sme + 83200);    // [2][128][40]
    float* bias_s = (float*)(sme + 83200 + 20480);        // [80]

    int tid = threadIdx.x, lane = tid & 31, warp = tid >> 5;
    int r0 = blockIdx.x * 128;

    if (tid < 80) bias_s[tid] = (tid < NTAG) ? bout[tid] : 0.f;

    unsigned BsB = smem_u32(Bs), AsB = smem_u32(As);

    #pragma unroll
    for (int i = 0; i < 20; i++) {
        int ch = tid + i * 256;            // 0..5119
        int j = ch >> 6, ko = (ch & 63) * 8;
        cpasync16(BsB + (unsigned)(j * BST + ko) * 2, d_WoutBf + (size_t)j * EDIM + ko);
    }
    #pragma unroll
    for (int i = 0; i < 2; i++) {
        int ch = tid + i * 256;            // 0..511
        int row = ch >> 2, ko = (ch & 3) * 8;
        cpasync16(AsB + (unsigned)(row * 40 + ko) * 2,
                  d_Hh + (size_t)(r0 + row) * 512 + ko);
    }
    CP_COMMIT();

    float acc[10][4];
    #pragma unroll
    for (int f = 0; f < 10; f++)
        #pragma unroll
        for (int q = 0; q < 4; q++) acc[f][q] = 0.f;

    unsigned aoffE = AsB + (unsigned)((warp * 16 + (lane & 15)) * 40 + (lane >> 4) * 8) * 2;
    unsigned boffE = BsB + (unsigned)(((lane & 7) + ((lane >> 4) * 8)) * BST
                                      + ((lane >> 3) & 1) * 8) * 2;

    for (int kc = 0; kc < 16; kc++) {
        int buf = kc & 1;
        if (kc < 15) {
            int nb = (kc + 1) & 1;
            #pragma unroll
            for (int i = 0; i < 2; i++) {
                int ch = tid + i * 256;
                int row = ch >> 2, ko = (ch & 3) * 8;
                cpasync16(AsB + (unsigned)(nb * 5120 + row * 40 + ko) * 2,
                          d_Hh + (size_t)(r0 + row) * 512 + (kc + 1) * 32 + ko);
            }
            CP_COMMIT();
            CP_WAIT(1);
        } else {
            CP_WAIT(0);
        }
        __syncthreads();

        #pragma unroll
        for (int kk = 0; kk < 2; kk++) {
            unsigned a[4];
            ldsm4(a[0], a[1], a[2], a[3], aoffE + (unsigned)(buf * 5120) * 2 + kk * 32);
            unsigned bq[5][4];
            #pragma unroll
            for (int p = 0; p < 5; p++)
                ldsm4(bq[p][0], bq[p][1], bq[p][2], bq[p][3],
                      boffE + (unsigned)(p * 16 * BST + kc * 32 + kk * 16) * 2);
            #pragma unroll
            for (int f = 0; f < 10; f++) {
                unsigned bb[2] = { bq[f >> 1][(f & 1) * 2], bq[f >> 1][(f & 1) * 2 + 1] };
                mma16816(acc[f], a, bb);
            }
        }
        __syncthreads();
    }

    #pragma unroll
    for (int f = 0; f < 10; f++) {
        int colb = f * 8 + (lane & 3) * 2;
        #pragma unroll
        for (int q = 0; q < 4; q++) {
            int cc = colb + (q & 1);
            if (cc < NTAG) {
                int r = r0 + warp * 16 + (lane >> 2) + (q >> 1) * 8;
                d_em[(size_t)r * NTAG + cc] = acc[f][q] + bias_s[cc];
            }
        }
    }
}

// ---------------- CRF: one block per batch element (R13) ----------------
__global__ void __launch_bounds__(128) k_crf(
    const int* __restrict__ tag_ids, const int* __restrict__ lengths,
    const float* __restrict__ start, const float* __restrict__ endt,
    const float* __restrict__ trans)
{
    __shared__ float E[NTAG * NTAG];
    __shared__ float alpha[128];
    __shared__ float p[128];
    __shared__ float red[128];
    int b = blockIdx.x;
    int tid = threadIdx.x;
    int len = lengths[b];

    for (int i = tid; i < NTAG * NTAG; i += 128) E[i] = __expf(trans[i]);

    float part = 0.f;
    if (tid >= 1 && tid < len) {
        int tg = tag_ids[b * SEQ + tid];
        int pv = tag_ids[b * SEQ + tid - 1];
        part = trans[pv * NTAG + tg] + d_em[(size_t)(tid * BATCH + b) * NTAG + tg];
    }
    if (tid == 0) {
        int t0 = tag_ids[b * SEQ];
        part += start[t0] + d_em[(size_t)b * NTAG + t0];
        part += endt[tag_ids[b * SEQ + len - 1]];
    }
    red[tid] = part;
    alpha[tid] = (tid < NTAG) ? start[tid] + d_em[(size_t)b * NTAG + tid] : 0.f;
    __syncthreads();
    for (int s2 = 64; s2 > 0; s2 >>= 1) {
        if (tid < s2) red[tid] += red[tid + s2];
        __syncthreads();
    }
    float score = red[0];

    for (int t = 1; t < len; t++) {
        float m = alpha[0];
        p[tid] = (tid < NTAG) ? __expf(alpha[tid] - m) : 0.f;
        __syncthreads();
        if (tid < NTAG) {
            float s0 = 0.f, s1 = 0.f, s2 = 0.f, s3 = 0.f;
            #pragma unroll
            for (int i = 0; i < NTAG; i += 4) {
                s0 = fmaf(p[i],     E[(i)     * NTAG + tid], s0);
                s1 = fmaf(p[i + 1], E[(i + 1) * NTAG + tid], s1);
                s2 = fmaf(p[i + 2], E[(i + 2) * NTAG + tid], s2);
                s3 = fmaf(p[i + 3], E[(i + 3) * NTAG + tid], s3);
            }
            alpha[tid] = m + __logf((s0 + s1) + (s2 + s3))
                         + d_em[(size_t)(t * BATCH + b) * NTAG + tid];
        }
        __syncthreads();
    }

    float m = alpha[0] + endt[0];
    p[tid] = (tid < NTAG) ? __expf(alpha[tid] + endt[tid] - m) : 0.f;
    __syncthreads();
    for (int s2 = 64; s2 > 0; s2 >>= 1) {
        if (tid < s2) p[tid] += p[tid + s2];
        __syncthreads();
    }
    if (tid == 0) d_llh[b] = score - (m + __logf(p[0]));
}

// ---------------- final reduce: out = -mean(llh) ----------------
__global__ void k_reduce(float* __restrict__ out)
{
    __shared__ float red[256];
    int tid = threadIdx.x;
    red[tid] = d_llh[tid];
    __syncthreads();
    for (int s = 128; s > 0; s >>= 1) {
        if (tid < s) red[tid] += red[tid + s];
        __syncthreads();
    }
    if (tid == 0) out[0] = -red[0] / 256.f;
}

extern "C" void kernel_launch(void* const* d_in, const int* in_sizes, int n_in,
                              void* d_out, int out_size)
{
    const int*   ids   = (const int*)d_in[0];
    const int*   tags  = (const int*)d_in[1];
    const int*   lens  = (const int*)d_in[2];
    const float* embed = (const float*)d_in[3];
    const float* Wihf  = (const float*)d_in[4];
    const float* Whhf  = (const float*)d_in[5];
    const float* bihf  = (const float*)d_in[6];
    const float* bhhf  = (const float*)d_in[7];
    const float* Wihb  = (const float*)d_in[8];
    const float* Whhb  = (const float*)d_in[9];
    const float* bihb  = (const float*)d_in[10];
    const float* bhhb  = (const float*)d_in[11];
    const float* Wout  = (const float*)d_in[12];
    const float* bout  = (const float*)d_in[13];
    const float* start = (const float*)d_in[14];
    const float* endt  = (const float*)d_in[15];
    const float* trans = (const float*)d_in[16];
    const float* h0    = (const float*)d_in[17];
    const float* c0    = (const float*)d_in[18];
    float* out = (float*)d_out;

    const int RSMEM = 128 * WST * 2;              // Wsb(64) + Hsm(64) rows, bf16
    const int ESMEM = 83200 + 20480 + 320;        // Bs + As + bias
    const int ZSMEM = 6 * 10240 + 512;            // 3-stage A+B + bias
    cudaFuncSetAttribute(k_recurrent, cudaFuncAttributeMaxDynamicSharedMemorySize, RSMEM);
    cudaFuncSetAttribute(k_recurrent, cudaFuncAttributeNonPortableClusterSizeAllowed, 1);
    cudaFuncSetAttribute(k_emis, cudaFuncAttributeMaxDynamicSharedMemorySize, ESMEM);
    cudaFuncSetAttribute(k_zmma, cudaFuncAttributeMaxDynamicSharedMemorySize, ZSMEM);

    k_init<<<512, 256>>>(h0);
    k_convW<<<2048, 128>>>(Wihf, Wihb, bihf, bhhf, bihb, bhhb);
    k_convO<<<80, 128>>>(Wout);
    k_gatherA<<<MROWS, 128>>>(ids, embed);
    k_zmma<<<dim3(16, 256), 256, ZSMEM>>>();
    k_recurrent<<<128, 128, RSMEM>>>(Whhf, Whhb, c0);
    k_emis<<<256, 256, ESMEM>>>(bout);
    k_crf<<<256, 128>>>(tags, lens, start, endt, trans);
    k_reduce<<<1, 256>>>(out);
}